// round 14
// baseline (speedup 1.0000x reference)
#include <cuda_runtime.h>
#include <cuda_bf16.h>
#include <cstdint>

#define NN 16384
#define NE 262144
#define HH 4
#define FF 128
#define D1 512          // HEADS*HID
#define SLOPE 0.2f
#define SK 32           // split-K factor for head GEMM

// ---------------- scratch (static device allocations) ----------------
__device__ float g_fs1[(size_t)NN * D1];
__device__ float g_fd1[(size_t)NN * D1];
__device__ float g_h1 [(size_t)NN * D1];
__device__ float g_fs2[(size_t)NN * FF];
__device__ float g_fd2[(size_t)NN * FF];
__device__ float g_h2 [(size_t)NN * FF];
__device__ float g_sc1[(size_t)NE * HH];
__device__ float g_sc2[NE];
__device__ float g_part[(size_t)SK * 256 * 128];
__device__ int   g_cnt[NN];
__device__ int   g_cur[NN];
__device__ int   g_rs [NN + 1];
__device__ int   g_eid[NE];
// bf16 hi/lo pair buffers (uint32 = bf16x2 of k-pair)
__device__ uint32_t g_fahi[(size_t)NN * 64];    // feat  [NN][K/2], K=128
__device__ uint32_t g_falo[(size_t)NN * 64];
__device__ uint32_t g_h1hi[(size_t)NN * 256];   // h1    [NN][K/2], K=512
__device__ uint32_t g_h1lo[(size_t)NN * 256];
__device__ uint32_t g_wshi[32768], g_wslo[32768];   // W*s transposed [N][K/2]
__device__ uint32_t g_wdhi[32768], g_wdlo[32768];   // W*d transposed [N][K/2]

__device__ __forceinline__ float lrelu(float x) { return x > 0.f ? x : SLOPE * x; }
__device__ __forceinline__ float elu_f(float x) { return x > 0.f ? x : expm1f(x); }

// split fp32 pair -> bf16x2 (hi) and bf16x2 (residual lo); low half = first elem
__device__ __forceinline__ void split_pack(float x0, float x1, uint32_t& hi, uint32_t& lo)
{
    __nv_bfloat16 h0 = __float2bfloat16(x0);
    __nv_bfloat16 h1 = __float2bfloat16(x1);
    __nv_bfloat16 l0 = __float2bfloat16(x0 - __bfloat162float(h0));
    __nv_bfloat16 l1 = __float2bfloat16(x1 - __bfloat162float(h1));
    __nv_bfloat162 H = __halves2bfloat162(h0, h1);
    __nv_bfloat162 L = __halves2bfloat162(l0, l1);
    hi = *reinterpret_cast<uint32_t*>(&H);
    lo = *reinterpret_cast<uint32_t*>(&L);
}

// ---- conversion kernels ----
// A [M x K] fp32 row-major -> hi/lo [M x K/2] uint32
__global__ void conv_a(const float* __restrict__ A, uint32_t* __restrict__ hi,
                       uint32_t* __restrict__ lo, int total /* M*K/2 */, int unused)
{
    int p = blockIdx.x * blockDim.x + threadIdx.x;
    if (p >= total) return;
    float2 v = *(const float2*)&A[(size_t)p * 2];
    uint32_t h, l;
    split_pack(v.x, v.y, h, l);
    hi[p] = h; lo[p] = l;
}
// W [K x N] fp32 -> transposed hi/lo [N x K/2]
__global__ void conv_w(const float* __restrict__ W, uint32_t* __restrict__ hi,
                       uint32_t* __restrict__ lo, int N, int Kw /* K/2 */)
{
    int idx = blockIdx.x * blockDim.x + threadIdx.x;
    if (idx >= N * Kw) return;
    int n = idx / Kw, j = idx % Kw;
    float w0 = W[(size_t)(2 * j)     * N + n];
    float w1 = W[(size_t)(2 * j + 1) * N + n];
    uint32_t h, l;
    split_pack(w0, w1, h, l);
    hi[idx] = h; lo[idx] = l;
}

// m16n8k16 row.col bf16 mma, fp32 accumulate (sm_80+ baseline PTX)
__device__ __forceinline__ void mma16816(float* d, const uint32_t* a, const uint32_t* b)
{
    asm volatile(
        "mma.sync.aligned.m16n8k16.row.col.f32.bf16.bf16.f32 "
        "{%0,%1,%2,%3}, {%4,%5,%6,%7}, {%8,%9}, {%0,%1,%2,%3};"
        : "+f"(d[0]), "+f"(d[1]), "+f"(d[2]), "+f"(d[3])
        : "r"(a[0]), "r"(a[1]), "r"(a[2]), "r"(a[3]), "r"(b[0]), "r"(b[1]));
}

// ============ mma.sync GEMM on pre-converted bf16 hi/lo operands ============
// C[M,N] = A @ W + bias; A as [M][K/2] hi/lo words, B as [N][K/2] hi/lo words.
// 128x128 block tile, 8 warps (4m x 2n), warp tile 32x64, K chunk 32.
#define LDA 18   // uint32 words per smem row: 16 pairs (32 bf16) + 2 pad

__global__ __launch_bounds__(256) void gemm_mma2(
    const uint32_t* __restrict__ Ahi, const uint32_t* __restrict__ Alo,
    const uint32_t* __restrict__ Bhi, const uint32_t* __restrict__ Blo,
    const float* __restrict__ bias, float* __restrict__ C,
    int M, int N, int K)
{
    __shared__ uint32_t sAhi[128 * LDA], sAlo[128 * LDA];
    __shared__ uint32_t sBhi[128 * LDA], sBlo[128 * LDA];

    const int tid  = threadIdx.x;
    const int wid  = tid >> 5;
    const int lane = tid & 31;
    const int m0   = blockIdx.y * 128;
    const int n0   = blockIdx.x * 128;
    const int wm   = wid >> 1;
    const int wn   = wid & 1;
    const int lr   = lane >> 2;
    const int lc   = lane & 3;
    const int Kw   = K >> 1;
    const int srow = tid >> 4;     // 0..15
    const int skp  = tid & 15;     // 0..15

    float d[2][8][4] = {};

    for (int kc = 0; kc < K; kc += 32) {
        const int kcw = kc >> 1;
        #pragma unroll
        for (int i = 0; i < 8; i++) {
            int row = srow + 16 * i;
            size_t ga = (size_t)(m0 + row) * Kw + kcw + skp;
            size_t gb = (size_t)(n0 + row) * Kw + kcw + skp;
            int so = row * LDA + skp;
            sAhi[so] = Ahi[ga];
            sAlo[so] = Alo[ga];
            sBhi[so] = Bhi[gb];
            sBlo[so] = Blo[gb];
        }
        __syncthreads();

        #pragma unroll
        for (int ks = 0; ks < 2; ks++) {
            const int kb = ks * 8;
            uint32_t ahi[2][4], alo[2][4];
            #pragma unroll
            for (int mt = 0; mt < 2; mt++) {
                int r = (wm * 32 + mt * 16 + lr) * LDA + kb + lc;
                ahi[mt][0] = sAhi[r];               alo[mt][0] = sAlo[r];
                ahi[mt][1] = sAhi[r + 8 * LDA];     alo[mt][1] = sAlo[r + 8 * LDA];
                ahi[mt][2] = sAhi[r + 4];           alo[mt][2] = sAlo[r + 4];
                ahi[mt][3] = sAhi[r + 8 * LDA + 4]; alo[mt][3] = sAlo[r + 8 * LDA + 4];
            }
            uint32_t bhi[8][2], blo[8][2];
            #pragma unroll
            for (int nt = 0; nt < 8; nt++) {
                int r = (wn * 64 + nt * 8 + lr) * LDA + kb + lc;
                bhi[nt][0] = sBhi[r];     blo[nt][0] = sBlo[r];
                bhi[nt][1] = sBhi[r + 4]; blo[nt][1] = sBlo[r + 4];
            }
            #pragma unroll
            for (int mt = 0; mt < 2; mt++)
                #pragma unroll
                for (int nt = 0; nt < 8; nt++) {
                    mma16816(d[mt][nt], ahi[mt], bhi[nt]);
                    mma16816(d[mt][nt], ahi[mt], blo[nt]);
                    mma16816(d[mt][nt], alo[mt], bhi[nt]);
                }
        }
        __syncthreads();
    }

    #pragma unroll
    for (int mt = 0; mt < 2; mt++) {
        int m = m0 + wm * 32 + mt * 16 + lr;
        #pragma unroll
        for (int nt = 0; nt < 8; nt++) {
            int col = n0 + wn * 64 + nt * 8 + 2 * lc;
            float2 bv = *(const float2*)&bias[col];
            float2 o0 = make_float2(d[mt][nt][0] + bv.x, d[mt][nt][1] + bv.y);
            float2 o1 = make_float2(d[mt][nt][2] + bv.x, d[mt][nt][3] + bv.y);
            *(float2*)&C[(size_t)m * N + col]       = o0;
            *(float2*)&C[(size_t)(m + 8) * N + col] = o1;
        }
    }
}

// ============ Split-K GEMM partial (head) ============
__global__ __launch_bounds__(256) void gemm_sk(
    const float* __restrict__ A, const float* __restrict__ B,
    float* __restrict__ P, int M, int N, int K, int kchunk)
{
    __shared__ float As[2][16][128];
    __shared__ float Bs[2][16][128];
    const int tid  = threadIdx.x;
    const int m0   = blockIdx.y * 128;
    const int n0   = blockIdx.x * 128;
    const int kz   = blockIdx.z * kchunk;
    const int la_m = tid >> 1;
    const int la_k = (tid & 1) << 3;
    const int lb_k = tid >> 4;
    const int lb_n = (tid & 15) << 3;
    const int ty   = tid >> 4;
    const int tx   = tid & 15;

    const float* Ap = A + (size_t)(m0 + la_m) * K + kz + la_k;
    const float* Bp = B + (size_t)(kz + lb_k) * N + n0 + lb_n;

    float4 ra0 = *(const float4*)(Ap);
    float4 ra1 = *(const float4*)(Ap + 4);
    float4 rb0 = *(const float4*)(Bp);
    float4 rb1 = *(const float4*)(Bp + 4);

    float acc[8][8] = {};

    As[0][la_k + 0][la_m] = ra0.x; As[0][la_k + 1][la_m] = ra0.y;
    As[0][la_k + 2][la_m] = ra0.z; As[0][la_k + 3][la_m] = ra0.w;
    As[0][la_k + 4][la_m] = ra1.x; As[0][la_k + 5][la_m] = ra1.y;
    As[0][la_k + 6][la_m] = ra1.z; As[0][la_k + 7][la_m] = ra1.w;
    *(float4*)&Bs[0][lb_k][lb_n]     = rb0;
    *(float4*)&Bs[0][lb_k][lb_n + 4] = rb1;
    __syncthreads();

    const int nsteps = kchunk >> 4;
    for (int s = 0; s < nsteps; s++) {
        const int buf = s & 1;
        if (s + 1 < nsteps) {
            const float* Ap2 = Ap + (s + 1) * 16;
            const float* Bp2 = Bp + (size_t)(s + 1) * 16 * N;
            ra0 = *(const float4*)(Ap2);
            ra1 = *(const float4*)(Ap2 + 4);
            rb0 = *(const float4*)(Bp2);
            rb1 = *(const float4*)(Bp2 + 4);
        }
        #pragma unroll
        for (int k = 0; k < 16; k++) {
            float a[8], b[8];
            *(float4*)&a[0] = *(const float4*)&As[buf][k][ty * 8];
            *(float4*)&a[4] = *(const float4*)&As[buf][k][ty * 8 + 4];
            *(float4*)&b[0] = *(const float4*)&Bs[buf][k][tx * 8];
            *(float4*)&b[4] = *(const float4*)&Bs[buf][k][tx * 8 + 4];
            #pragma unroll
            for (int i = 0; i < 8; i++)
                #pragma unroll
                for (int j = 0; j < 8; j++)
                    acc[i][j] = fmaf(a[i], b[j], acc[i][j]);
        }
        if (s + 1 < nsteps) {
            const int nb = buf ^ 1;
            As[nb][la_k + 0][la_m] = ra0.x; As[nb][la_k + 1][la_m] = ra0.y;
            As[nb][la_k + 2][la_m] = ra0.z; As[nb][la_k + 3][la_m] = ra0.w;
            As[nb][la_k + 4][la_m] = ra1.x; As[nb][la_k + 5][la_m] = ra1.y;
            As[nb][la_k + 6][la_m] = ra1.z; As[nb][la_k + 7][la_m] = ra1.w;
            *(float4*)&Bs[nb][lb_k][lb_n]     = rb0;
            *(float4*)&Bs[nb][lb_k][lb_n + 4] = rb1;
        }
        __syncthreads();
    }

    float* Pz = P + (size_t)blockIdx.z * M * N;
    #pragma unroll
    for (int i = 0; i < 8; i++) {
        float* cp = Pz + (size_t)(m0 + ty * 8 + i) * N + n0 + tx * 8;
        *(float4*)cp       = make_float4(acc[i][0], acc[i][1], acc[i][2], acc[i][3]);
        *(float4*)(cp + 4) = make_float4(acc[i][4], acc[i][5], acc[i][6], acc[i][7]);
    }
}

__global__ void sk_reduce(const float* __restrict__ P, const float* __restrict__ bias,
                          float* __restrict__ C, int MN, int N, int nz)
{
    int i = blockIdx.x * blockDim.x + threadIdx.x;
    if (i >= MN) return;
    float s = 0.f;
    for (int z = 0; z < nz; z++) s += P[(size_t)z * MN + i];
    C[i] = s + bias[i % N];
}

// ---------------- CSR build (group edges by dst) ----------------
__global__ void csr_zero()
{
    int i = blockIdx.x * blockDim.x + threadIdx.x;
    if (i < NN) { g_cnt[i] = 0; g_cur[i] = 0; }
}
__global__ void csr_hist(const int* __restrict__ dst)
{
    int e = blockIdx.x * blockDim.x + threadIdx.x;
    if (e < NE) atomicAdd(&g_cnt[dst[e]], 1);
}
__global__ void csr_scan()
{
    __shared__ int sh[1024];
    int t = threadIdx.x;
    int base = t * 16;
    int v[16];
    int s = 0;
    #pragma unroll
    for (int j = 0; j < 16; j++) { s += g_cnt[base + j]; v[j] = s; }
    sh[t] = s;
    __syncthreads();
    for (int off = 1; off < 1024; off <<= 1) {
        int x = (t >= off) ? sh[t - off] : 0;
        __syncthreads();
        sh[t] += x;
        __syncthreads();
    }
    int excl = (t > 0) ? sh[t - 1] : 0;
    if (t == 0) g_rs[0] = 0;
    #pragma unroll
    for (int j = 0; j < 16; j++) g_rs[base + j + 1] = excl + v[j];
}
__global__ void csr_scatter(const int* __restrict__ dst)
{
    int e = blockIdx.x * blockDim.x + threadIdx.x;
    if (e < NE) {
        int d = dst[e];
        int p = atomicAdd(&g_cur[d], 1);
        g_eid[g_rs[d] + p] = e;
    }
}

// ---------------- layer-1 edge scores (CSR): block(128) per dst node ---------
__global__ void score1n(const int* __restrict__ src, const float* __restrict__ attn)
{
    int n    = blockIdx.x;
    int tid  = threadIdx.x;
    int lane = tid & 31;
    int h    = tid >> 5;
    __shared__ float sfd[D1];
    int rs = g_rs[n], re = g_rs[n + 1];

    *(float4*)&sfd[tid * 4] = *(const float4*)&g_fd1[(size_t)n * D1 + tid * 4];
    __syncthreads();
    float4 b = *(const float4*)&sfd[tid * 4];
    float4 w = ((const float4*)attn)[h * 32 + lane];

    for (int i = rs; i < re; i++) {
        int e = g_eid[i];
        float4 a = *(const float4*)&g_fs1[(size_t)src[e] * D1 + tid * 4];
        float v = lrelu(a.x + b.x) * w.x + lrelu(a.y + b.y) * w.y
                + lrelu(a.z + b.z) * w.z + lrelu(a.w + b.w) * w.w;
        #pragma unroll
        for (int o = 16; o; o >>= 1) v += __shfl_xor_sync(0xffffffffu, v, o);
        if (lane == 0) g_sc1[(size_t)e * HH + h] = v;
    }
}

// ---------------- layer-1 softmax + aggregation + ELU: block(128) per node ----
__global__ void agg1(const int* __restrict__ src)
{
    int n    = blockIdx.x;
    int tid  = threadIdx.x;
    int lane = tid & 31;
    int w    = tid >> 5;
    __shared__ float sm[HH], sinv[HH];
    int rs  = g_rs[n];
    int deg = g_rs[n + 1] - rs;

    float mx = -1e30f;
    for (int i = lane; i < deg; i += 32)
        mx = fmaxf(mx, g_sc1[(size_t)g_eid[rs + i] * HH + w]);
    #pragma unroll
    for (int o = 16; o; o >>= 1) mx = fmaxf(mx, __shfl_xor_sync(0xffffffffu, mx, o));
    float sum = 0.f;
    for (int i = lane; i < deg; i += 32)
        sum += __expf(g_sc1[(size_t)g_eid[rs + i] * HH + w] - mx);
    #pragma unroll
    for (int o = 16; o; o >>= 1) sum += __shfl_xor_sync(0xffffffffu, sum, o);
    if (lane == 0) { sm[w] = mx; sinv[w] = sum > 0.f ? 1.f / sum : 0.f; }
    __syncthreads();
    float m = sm[w], inv = sinv[w];

    float4 acc = make_float4(0.f, 0.f, 0.f, 0.f);
    for (int i = 0; i < deg; i++) {
        int e = g_eid[rs + i];
        float a = __expf(g_sc1[(size_t)e * HH + w] - m) * inv;
        float4 f = *(const float4*)(g_fs1 + (size_t)src[e] * D1 + tid * 4);
        acc.x = fmaf(a, f.x, acc.x);
        acc.y = fmaf(a, f.y, acc.y);
        acc.z = fmaf(a, f.z, acc.z);
        acc.w = fmaf(a, f.w, acc.w);
    }
    float4 o = make_float4(elu_f(acc.x), elu_f(acc.y), elu_f(acc.z), elu_f(acc.w));
    *(float4*)(g_h1 + (size_t)n * D1 + tid * 4) = o;
}

// ---------------- layer-2 edge scores (CSR): warp per dst node ----------------
__global__ void score2n(const int* __restrict__ src, const float* __restrict__ attn)
{
    int n    = blockIdx.x * 8 + (threadIdx.x >> 5);
    int lane = threadIdx.x & 31;
    int rs = g_rs[n], re = g_rs[n + 1];

    float4 b = *(const float4*)&g_fd2[(size_t)n * FF + lane * 4];
    float4 w = *(const float4*)(attn + lane * 4);

    for (int i = rs; i < re; i++) {
        int e = g_eid[i];
        float4 a = *(const float4*)&g_fs2[(size_t)src[e] * FF + lane * 4];
        float v = lrelu(a.x + b.x) * w.x + lrelu(a.y + b.y) * w.y
                + lrelu(a.z + b.z) * w.z + lrelu(a.w + b.w) * w.w;
        #pragma unroll
        for (int o = 16; o; o >>= 1) v += __shfl_xor_sync(0xffffffffu, v, o);
        if (lane == 0) g_sc2[e] = v;
    }
}

// ---------------- layer-2 softmax + aggregation + ELU: warp per node ----------
__global__ void agg2(const int* __restrict__ src)
{
    int n    = blockIdx.x * 8 + (threadIdx.x >> 5);
    int lane = threadIdx.x & 31;
    int rs   = g_rs[n];
    int deg  = g_rs[n + 1] - rs;

    float mx = -1e30f;
    for (int i = lane; i < deg; i += 32)
        mx = fmaxf(mx, g_sc2[g_eid[rs + i]]);
    #pragma unroll
    for (int o = 16; o; o >>= 1) mx = fmaxf(mx, __shfl_xor_sync(0xffffffffu, mx, o));
    float sum = 0.f;
    for (int i = lane; i < deg; i += 32)
        sum += __expf(g_sc2[g_eid[rs + i]] - mx);
    #pragma unroll
    for (int o = 16; o; o >>= 1) sum += __shfl_xor_sync(0xffffffffu, sum, o);
    float inv = sum > 0.f ? 1.f / sum : 0.f;

    float4 acc = make_float4(0.f, 0.f, 0.f, 0.f);
    for (int i = 0; i < deg; i++) {
        int e = g_eid[rs + i];
        float a = __expf(g_sc2[e] - mx) * inv;
        float4 f = *(const float4*)(g_fs2 + (size_t)src[e] * FF + lane * 4);
        acc.x = fmaf(a, f.x, acc.x);
        acc.y = fmaf(a, f.y, acc.y);
        acc.z = fmaf(a, f.z, acc.z);
        acc.w = fmaf(a, f.w, acc.w);
    }
    float4 o = make_float4(elu_f(acc.x), elu_f(acc.y), elu_f(acc.z), elu_f(acc.w));
    *(float4*)(g_h2 + (size_t)n * FF + lane * 4) = o;
}

// ---------------- launch ----------------
extern "C" void kernel_launch(void* const* d_in, const int* in_sizes, int n_in,
                              void* d_out, int out_size)
{
    const float* feat  = (const float*)d_in[0];
    const int*   src   = (const int*)  d_in[1];
    const int*   dst   = (const int*)  d_in[2];
    const float* W1s   = (const float*)d_in[3];
    const float* b1s   = (const float*)d_in[4];
    const float* W1d   = (const float*)d_in[5];
    const float* b1d   = (const float*)d_in[6];
    const float* attn1 = (const float*)d_in[7];
    const float* W2s   = (const float*)d_in[8];
    const float* b2s   = (const float*)d_in[9];
    const float* W2d   = (const float*)d_in[10];
    const float* b2d   = (const float*)d_in[11];
    const float* attn2 = (const float*)d_in[12];
    const float* Wn    = (const float*)d_in[13];
    const float* bn    = (const float*)d_in[14];
    float* out = (float*)d_out;

    float *fs1, *fd1, *h1, *fs2, *fd2, *h2, *part;
    uint32_t *fahi, *falo, *h1hi, *h1lo, *wshi, *wslo, *wdhi, *wdlo;
    cudaGetSymbolAddress((void**)&fs1,  g_fs1);
    cudaGetSymbolAddress((void**)&fd1,  g_fd1);
    cudaGetSymbolAddress((void**)&h1,   g_h1);
    cudaGetSymbolAddress((void**)&fs2,  g_fs2);
    cudaGetSymbolAddress((void**)&fd2,  g_fd2);
    cudaGetSymbolAddress((void**)&h2,   g_h2);
    cudaGetSymbolAddress((void**)&part, g_part);
    cudaGetSymbolAddress((void**)&fahi, g_fahi);
    cudaGetSymbolAddress((void**)&falo, g_falo);
    cudaGetSymbolAddress((void**)&h1hi, g_h1hi);
    cudaGetSymbolAddress((void**)&h1lo, g_h1lo);
    cudaGetSymbolAddress((void**)&wshi, g_wshi);
    cudaGetSymbolAddress((void**)&wslo, g_wslo);
    cudaGetSymbolAddress((void**)&wdhi, g_wdhi);
    cudaGetSymbolAddress((void**)&wdlo, g_wdlo);

    // CSR build first (independent of GEMMs)
    csr_zero   <<<NN / 256, 256>>>();
    csr_hist   <<<NE / 256, 256>>>(dst);
    csr_scan   <<<1, 1024>>>();
    csr_scatter<<<NE / 256, 256>>>(dst);

    // pre-convert layer-1 operands
    conv_a<<<(NN * 64) / 256, 256>>>(feat, fahi, falo, NN * 64, 0);
    conv_w<<<(D1 * 64) / 256, 256>>>(W1s, wshi, wslo, D1, 64);
    conv_w<<<(D1 * 64) / 256, 256>>>(W1d, wdhi, wdlo, D1, 64);

    // layer-1 projections: [16384,128] @ [128,512]
    gemm_mma2<<<dim3(D1 / 128, NN / 128), 256>>>(fahi, falo, wshi, wslo, b1s, fs1, NN, D1, FF);
    gemm_mma2<<<dim3(D1 / 128, NN / 128), 256>>>(fahi, falo, wdhi, wdlo, b1d, fd1, NN, D1, FF);

    // layer-1 edge softmax + aggregation (+ ELU)
    score1n<<<NN, 128>>>(src, attn1);
    agg1   <<<NN, 128>>>(src);

    // pre-convert layer-2 operands
    conv_a<<<(NN * 256) / 256, 256>>>(h1, h1hi, h1lo, NN * 256, 0);
    conv_w<<<(FF * 256) / 256, 256>>>(W2s, wshi, wslo, FF, 256);
    conv_w<<<(FF * 256) / 256, 256>>>(W2d, wdhi, wdlo, FF, 256);

    // layer-2 projections: [16384,512] @ [512,128]
    gemm_mma2<<<dim3(FF / 128, NN / 128), 256>>>(h1hi, h1lo, wshi, wslo, b2s, fs2, NN, FF, D1);
    gemm_mma2<<<dim3(FF / 128, NN / 128), 256>>>(h1hi, h1lo, wdhi, wdlo, b2d, fd2, NN, FF, D1);

    // layer-2 edge softmax + aggregation (+ ELU)
    score2n<<<NN / 8, 256>>>(src, attn2);
    agg2   <<<NN / 8, 256>>>(src);

    // head: [256, 8192] @ [8192, 128] + bn — 32-way split-K then reduce
    gemm_sk<<<dim3(1, 2, SK), 256>>>(h2, Wn, part, 256, FF, 64 * FF, (64 * FF) / SK);
    sk_reduce<<<(256 * FF) / 256, 256>>>(part, bn, out, 256 * FF, FF, SK);
}

// round 15
// speedup vs baseline: 1.2870x; 1.2870x over previous
#include <cuda_runtime.h>
#include <cuda_bf16.h>
#include <cstdint>

#define NN 16384
#define NE 262144
#define HH 4
#define FF 128
#define D1 512          // HEADS*HID
#define SLOPE 0.2f
#define SK 32           // split-K factor for head GEMM

// ---------------- scratch (static device allocations) ----------------
__device__ float g_fs1[(size_t)NN * D1];
__device__ float g_fd1[(size_t)NN * D1];
__device__ float g_h1 [(size_t)NN * D1];
__device__ float g_fs2[(size_t)NN * FF];
__device__ float g_fd2[(size_t)NN * FF];
__device__ float g_h2 [(size_t)NN * FF];
__device__ float g_part[(size_t)SK * 256 * 128];
__device__ int   g_cnt[NN];
__device__ int   g_cur[NN];
__device__ int   g_rs [NN + 1];
__device__ int   g_eid[NE];

__device__ __forceinline__ float lrelu(float x) { return x > 0.f ? x : SLOPE * x; }
__device__ __forceinline__ float elu_f(float x) { return x > 0.f ? x : expm1f(x); }

// split fp32 pair -> bf16x2 (hi) and bf16x2 (residual lo); low half = first elem
__device__ __forceinline__ void split_pack(float x0, float x1, uint32_t& hi, uint32_t& lo)
{
    __nv_bfloat16 h0 = __float2bfloat16(x0);
    __nv_bfloat16 h1 = __float2bfloat16(x1);
    __nv_bfloat16 l0 = __float2bfloat16(x0 - __bfloat162float(h0));
    __nv_bfloat16 l1 = __float2bfloat16(x1 - __bfloat162float(h1));
    __nv_bfloat162 H = __halves2bfloat162(h0, h1);
    __nv_bfloat162 L = __halves2bfloat162(l0, l1);
    hi = *reinterpret_cast<uint32_t*>(&H);
    lo = *reinterpret_cast<uint32_t*>(&L);
}

// m16n8k16 row.col bf16 mma, fp32 accumulate (sm_80+ baseline PTX)
__device__ __forceinline__ void mma16816(float* d, const uint32_t* a, const uint32_t* b)
{
    asm volatile(
        "mma.sync.aligned.m16n8k16.row.col.f32.bf16.bf16.f32 "
        "{%0,%1,%2,%3}, {%4,%5,%6,%7}, {%8,%9}, {%0,%1,%2,%3};"
        : "+f"(d[0]), "+f"(d[1]), "+f"(d[2]), "+f"(d[3])
        : "r"(a[0]), "r"(a[1]), "r"(a[2]), "r"(a[3]), "r"(b[0]), "r"(b[1]));
}

// ============ mma.sync GEMM: C[M,N] = A[M,K] @ W[K,N] + bias ============
// (proven R12 version) 128x128 block tile, 8 warps (4m x 2n), K chunk 32.
#define LDA 18   // uint32 words per smem row: 16 pairs (32 bf16) + 2 pad

__global__ __launch_bounds__(256) void gemm_mma(
    const float* __restrict__ A, const float* __restrict__ W,
    const float* __restrict__ bias, float* __restrict__ C,
    int M, int N, int K)
{
    __shared__ uint32_t sAhi[128 * LDA], sAlo[128 * LDA];
    __shared__ uint32_t sBhi[128 * LDA], sBlo[128 * LDA];

    const int tid  = threadIdx.x;
    const int wid  = tid >> 5;
    const int lane = tid & 31;
    const int m0   = blockIdx.y * 128;
    const int n0   = blockIdx.x * 128;
    const int wm   = wid >> 1;
    const int wn   = wid & 1;
    const int lr   = lane >> 2;
    const int lc   = lane & 3;

    float d[2][8][4] = {};

    for (int kc = 0; kc < K; kc += 32) {
        #pragma unroll
        for (int i = 0; i < 8; i++) {
            int q = tid + 256 * i;
            int row = q >> 4, kp = q & 15;
            float2 v = *(const float2*)&A[(size_t)(m0 + row) * K + kc + 2 * kp];
            uint32_t hi, lo;
            split_pack(v.x, v.y, hi, lo);
            sAhi[row * LDA + kp] = hi;
            sAlo[row * LDA + kp] = lo;
        }
        #pragma unroll
        for (int i = 0; i < 8; i++) {
            int q = tid + 256 * i;
            int n = q & 127, jj = q >> 7;
            float w0 = W[(size_t)(kc + 2 * jj) * N + n0 + n];
            float w1 = W[(size_t)(kc + 2 * jj + 1) * N + n0 + n];
            uint32_t hi, lo;
            split_pack(w0, w1, hi, lo);
            sBhi[n * LDA + jj] = hi;
            sBlo[n * LDA + jj] = lo;
        }
        __syncthreads();

        #pragma unroll
        for (int ks = 0; ks < 2; ks++) {
            const int kb = ks * 8;
            uint32_t ahi[2][4], alo[2][4];
            #pragma unroll
            for (int mt = 0; mt < 2; mt++) {
                int r = (wm * 32 + mt * 16 + lr) * LDA + kb + lc;
                ahi[mt][0] = sAhi[r];               alo[mt][0] = sAlo[r];
                ahi[mt][1] = sAhi[r + 8 * LDA];     alo[mt][1] = sAlo[r + 8 * LDA];
                ahi[mt][2] = sAhi[r + 4];           alo[mt][2] = sAlo[r + 4];
                ahi[mt][3] = sAhi[r + 8 * LDA + 4]; alo[mt][3] = sAlo[r + 8 * LDA + 4];
            }
            uint32_t bhi[8][2], blo[8][2];
            #pragma unroll
            for (int nt = 0; nt < 8; nt++) {
                int r = (wn * 64 + nt * 8 + lr) * LDA + kb + lc;
                bhi[nt][0] = sBhi[r];     blo[nt][0] = sBlo[r];
                bhi[nt][1] = sBhi[r + 4]; blo[nt][1] = sBlo[r + 4];
            }
            #pragma unroll
            for (int mt = 0; mt < 2; mt++)
                #pragma unroll
                for (int nt = 0; nt < 8; nt++) {
                    mma16816(d[mt][nt], ahi[mt], bhi[nt]);
                    mma16816(d[mt][nt], ahi[mt], blo[nt]);
                    mma16816(d[mt][nt], alo[mt], bhi[nt]);
                }
        }
        __syncthreads();
    }

    #pragma unroll
    for (int mt = 0; mt < 2; mt++) {
        int m = m0 + wm * 32 + mt * 16 + lr;
        #pragma unroll
        for (int nt = 0; nt < 8; nt++) {
            int col = n0 + wn * 64 + nt * 8 + 2 * lc;
            float2 bv = *(const float2*)&bias[col];
            float2 o0 = make_float2(d[mt][nt][0] + bv.x, d[mt][nt][1] + bv.y);
            float2 o1 = make_float2(d[mt][nt][2] + bv.x, d[mt][nt][3] + bv.y);
            *(float2*)&C[(size_t)m * N + col]       = o0;
            *(float2*)&C[(size_t)(m + 8) * N + col] = o1;
        }
    }
}

// ============ Split-K GEMM partial (head) ============
__global__ __launch_bounds__(256) void gemm_sk(
    const float* __restrict__ A, const float* __restrict__ B,
    float* __restrict__ P, int M, int N, int K, int kchunk)
{
    __shared__ float As[2][16][128];
    __shared__ float Bs[2][16][128];
    const int tid  = threadIdx.x;
    const int m0   = blockIdx.y * 128;
    const int n0   = blockIdx.x * 128;
    const int kz   = blockIdx.z * kchunk;
    const int la_m = tid >> 1;
    const int la_k = (tid & 1) << 3;
    const int lb_k = tid >> 4;
    const int lb_n = (tid & 15) << 3;
    const int ty   = tid >> 4;
    const int tx   = tid & 15;

    const float* Ap = A + (size_t)(m0 + la_m) * K + kz + la_k;
    const float* Bp = B + (size_t)(kz + lb_k) * N + n0 + lb_n;

    float4 ra0 = *(const float4*)(Ap);
    float4 ra1 = *(const float4*)(Ap + 4);
    float4 rb0 = *(const float4*)(Bp);
    float4 rb1 = *(const float4*)(Bp + 4);

    float acc[8][8] = {};

    As[0][la_k + 0][la_m] = ra0.x; As[0][la_k + 1][la_m] = ra0.y;
    As[0][la_k + 2][la_m] = ra0.z; As[0][la_k + 3][la_m] = ra0.w;
    As[0][la_k + 4][la_m] = ra1.x; As[0][la_k + 5][la_m] = ra1.y;
    As[0][la_k + 6][la_m] = ra1.z; As[0][la_k + 7][la_m] = ra1.w;
    *(float4*)&Bs[0][lb_k][lb_n]     = rb0;
    *(float4*)&Bs[0][lb_k][lb_n + 4] = rb1;
    __syncthreads();

    const int nsteps = kchunk >> 4;
    for (int s = 0; s < nsteps; s++) {
        const int buf = s & 1;
        if (s + 1 < nsteps) {
            const float* Ap2 = Ap + (s + 1) * 16;
            const float* Bp2 = Bp + (size_t)(s + 1) * 16 * N;
            ra0 = *(const float4*)(Ap2);
            ra1 = *(const float4*)(Ap2 + 4);
            rb0 = *(const float4*)(Bp2);
            rb1 = *(const float4*)(Bp2 + 4);
        }
        #pragma unroll
        for (int k = 0; k < 16; k++) {
            float a[8], b[8];
            *(float4*)&a[0] = *(const float4*)&As[buf][k][ty * 8];
            *(float4*)&a[4] = *(const float4*)&As[buf][k][ty * 8 + 4];
            *(float4*)&b[0] = *(const float4*)&Bs[buf][k][tx * 8];
            *(float4*)&b[4] = *(const float4*)&Bs[buf][k][tx * 8 + 4];
            #pragma unroll
            for (int i = 0; i < 8; i++)
                #pragma unroll
                for (int j = 0; j < 8; j++)
                    acc[i][j] = fmaf(a[i], b[j], acc[i][j]);
        }
        if (s + 1 < nsteps) {
            const int nb = buf ^ 1;
            As[nb][la_k + 0][la_m] = ra0.x; As[nb][la_k + 1][la_m] = ra0.y;
            As[nb][la_k + 2][la_m] = ra0.z; As[nb][la_k + 3][la_m] = ra0.w;
            As[nb][la_k + 4][la_m] = ra1.x; As[nb][la_k + 5][la_m] = ra1.y;
            As[nb][la_k + 6][la_m] = ra1.z; As[nb][la_k + 7][la_m] = ra1.w;
            *(float4*)&Bs[nb][lb_k][lb_n]     = rb0;
            *(float4*)&Bs[nb][lb_k][lb_n + 4] = rb1;
        }
        __syncthreads();
    }

    float* Pz = P + (size_t)blockIdx.z * M * N;
    #pragma unroll
    for (int i = 0; i < 8; i++) {
        float* cp = Pz + (size_t)(m0 + ty * 8 + i) * N + n0 + tx * 8;
        *(float4*)cp       = make_float4(acc[i][0], acc[i][1], acc[i][2], acc[i][3]);
        *(float4*)(cp + 4) = make_float4(acc[i][4], acc[i][5], acc[i][6], acc[i][7]);
    }
}

__global__ void sk_reduce(const float* __restrict__ P, const float* __restrict__ bias,
                          float* __restrict__ C, int MN, int N, int nz)
{
    int i = blockIdx.x * blockDim.x + threadIdx.x;
    if (i >= MN) return;
    float s = 0.f;
    for (int z = 0; z < nz; z++) s += P[(size_t)z * MN + i];
    C[i] = s + bias[i % N];
}

// ---------------- CSR build (group edges by dst) ----------------
__global__ void csr_zero()
{
    int i = blockIdx.x * blockDim.x + threadIdx.x;
    if (i < NN) { g_cnt[i] = 0; g_cur[i] = 0; }
}
__global__ void csr_hist(const int* __restrict__ dst)
{
    int e = blockIdx.x * blockDim.x + threadIdx.x;
    if (e < NE) atomicAdd(&g_cnt[dst[e]], 1);
}
__global__ void csr_scan()
{
    __shared__ int sh[1024];
    int t = threadIdx.x;
    int base = t * 16;
    int v[16];
    int s = 0;
    #pragma unroll
    for (int j = 0; j < 16; j++) { s += g_cnt[base + j]; v[j] = s; }
    sh[t] = s;
    __syncthreads();
    for (int off = 1; off < 1024; off <<= 1) {
        int x = (t >= off) ? sh[t - off] : 0;
        __syncthreads();
        sh[t] += x;
        __syncthreads();
    }
    int excl = (t > 0) ? sh[t - 1] : 0;
    if (t == 0) g_rs[0] = 0;
    #pragma unroll
    for (int j = 0; j < 16; j++) g_rs[base + j + 1] = excl + v[j];
}
__global__ void csr_scatter(const int* __restrict__ dst)
{
    int e = blockIdx.x * blockDim.x + threadIdx.x;
    if (e < NE) {
        int d = dst[e];
        int p = atomicAdd(&g_cur[d], 1);
        g_eid[g_rs[d] + p] = e;
    }
}

// ======== layer-1 fused score + online-softmax + aggregation + ELU ========
// block(128) per dst node; warp h owns head h (features h*128 .. h*128+127).
__global__ void agg1f(const int* __restrict__ src, const float* __restrict__ attn)
{
    int n    = blockIdx.x;
    int tid  = threadIdx.x;
    int h    = tid >> 5;
    int lane = tid & 31;
    int rs = g_rs[n], re = g_rs[n + 1];

    float4 b = *(const float4*)&g_fd1[(size_t)n * D1 + tid * 4];
    float4 w = ((const float4*)attn)[h * 32 + lane];

    float m = -1e30f, s = 0.f;
    float4 acc = make_float4(0.f, 0.f, 0.f, 0.f);

    for (int i = rs; i < re; i++) {
        int e = g_eid[i];
        float4 f = *(const float4*)&g_fs1[(size_t)src[e] * D1 + tid * 4];
        float v = lrelu(f.x + b.x) * w.x + lrelu(f.y + b.y) * w.y
                + lrelu(f.z + b.z) * w.z + lrelu(f.w + b.w) * w.w;
        #pragma unroll
        for (int o = 16; o; o >>= 1) v += __shfl_xor_sync(0xffffffffu, v, o);
        if (v > m) {
            float c = __expf(m - v);
            s *= c;
            acc.x *= c; acc.y *= c; acc.z *= c; acc.w *= c;
            m = v;
        }
        float p = __expf(v - m);
        s += p;
        acc.x = fmaf(p, f.x, acc.x);
        acc.y = fmaf(p, f.y, acc.y);
        acc.z = fmaf(p, f.z, acc.z);
        acc.w = fmaf(p, f.w, acc.w);
    }
    float inv = s > 0.f ? 1.f / s : 0.f;
    float4 o = make_float4(elu_f(acc.x * inv), elu_f(acc.y * inv),
                           elu_f(acc.z * inv), elu_f(acc.w * inv));
    *(float4*)(g_h1 + (size_t)n * D1 + tid * 4) = o;
}

// ======== layer-2 fused score + online-softmax + aggregation + ELU ========
// warp per dst node (single head, 128 features).
__global__ void agg2f(const int* __restrict__ src, const float* __restrict__ attn)
{
    int n    = blockIdx.x * 8 + (threadIdx.x >> 5);
    int lane = threadIdx.x & 31;
    int rs = g_rs[n], re = g_rs[n + 1];

    float4 b = *(const float4*)&g_fd2[(size_t)n * FF + lane * 4];
    float4 w = *(const float4*)(attn + lane * 4);

    float m = -1e30f, s = 0.f;
    float4 acc = make_float4(0.f, 0.f, 0.f, 0.f);

    for (int i = rs; i < re; i++) {
        int e = g_eid[i];
        float4 f = *(const float4*)&g_fs2[(size_t)src[e] * FF + lane * 4];
        float v = lrelu(f.x + b.x) * w.x + lrelu(f.y + b.y) * w.y
                + lrelu(f.z + b.z) * w.z + lrelu(f.w + b.w) * w.w;
        #pragma unroll
        for (int o = 16; o; o >>= 1) v += __shfl_xor_sync(0xffffffffu, v, o);
        if (v > m) {
            float c = __expf(m - v);
            s *= c;
            acc.x *= c; acc.y *= c; acc.z *= c; acc.w *= c;
            m = v;
        }
        float p = __expf(v - m);
        s += p;
        acc.x = fmaf(p, f.x, acc.x);
        acc.y = fmaf(p, f.y, acc.y);
        acc.z = fmaf(p, f.z, acc.z);
        acc.w = fmaf(p, f.w, acc.w);
    }
    float inv = s > 0.f ? 1.f / s : 0.f;
    float4 o = make_float4(elu_f(acc.x * inv), elu_f(acc.y * inv),
                           elu_f(acc.z * inv), elu_f(acc.w * inv));
    *(float4*)(g_h2 + (size_t)n * FF + lane * 4) = o;
}

// ---------------- launch ----------------
extern "C" void kernel_launch(void* const* d_in, const int* in_sizes, int n_in,
                              void* d_out, int out_size)
{
    const float* feat  = (const float*)d_in[0];
    const int*   src   = (const int*)  d_in[1];
    const int*   dst   = (const int*)  d_in[2];
    const float* W1s   = (const float*)d_in[3];
    const float* b1s   = (const float*)d_in[4];
    const float* W1d   = (const float*)d_in[5];
    const float* b1d   = (const float*)d_in[6];
    const float* attn1 = (const float*)d_in[7];
    const float* W2s   = (const float*)d_in[8];
    const float* b2s   = (const float*)d_in[9];
    const float* W2d   = (const float*)d_in[10];
    const float* b2d   = (const float*)d_in[11];
    const float* attn2 = (const float*)d_in[12];
    const float* Wn    = (const float*)d_in[13];
    const float* bn    = (const float*)d_in[14];
    float* out = (float*)d_out;

    float *fs1, *fd1, *h1, *fs2, *fd2, *h2, *part;
    cudaGetSymbolAddress((void**)&fs1,  g_fs1);
    cudaGetSymbolAddress((void**)&fd1,  g_fd1);
    cudaGetSymbolAddress((void**)&h1,   g_h1);
    cudaGetSymbolAddress((void**)&fs2,  g_fs2);
    cudaGetSymbolAddress((void**)&fd2,  g_fd2);
    cudaGetSymbolAddress((void**)&h2,   g_h2);
    cudaGetSymbolAddress((void**)&part, g_part);

    // CSR build (independent of GEMMs)
    csr_zero   <<<NN / 256, 256>>>();
    csr_hist   <<<NE / 256, 256>>>(dst);
    csr_scan   <<<1, 1024>>>();
    csr_scatter<<<NE / 256, 256>>>(dst);

    // layer-1 projections: [16384,128] @ [128,512]  (mma.sync bf16 3-term)
    gemm_mma<<<dim3(D1 / 128, NN / 128), 256>>>(feat, W1s, b1s, fs1, NN, D1, FF);
    gemm_mma<<<dim3(D1 / 128, NN / 128), 256>>>(feat, W1d, b1d, fd1, NN, D1, FF);

    // layer-1 fused edge pass
    agg1f<<<NN, 128>>>(src, attn1);

    // layer-2 projections: [16384,512] @ [512,128]
    gemm_mma<<<dim3(FF / 128, NN / 128), 256>>>(h1, W2s, b2s, fs2, NN, FF, D1);
    gemm_mma<<<dim3(FF / 128, NN / 128), 256>>>(h1, W2d, b2d, fd2, NN, FF, D1);

    // layer-2 fused edge pass
    agg2f<<<NN / 8, 256>>>(src, attn2);

    // head: [256, 8192] @ [8192, 128] + bn — 32-way split-K then reduce
    gemm_sk<<<dim3(1, 2, SK), 256>>>(h2, Wn, part, 256, FF, 64 * FF, (64 * FF) / SK);
    sk_reduce<<<(256 * FF) / 256, 256>>>(part, bn, out, 256 * FF, FF, SK);
}